// round 16
// baseline (speedup 1.0000x reference)
#include <cuda_runtime.h>
#include <cuda_fp16.h>
#include <cstdint>
#include <math.h>

// ---------------------------------------------------------------------------
// Transformer encoder layer. All GEMMs + attention on mma.sync fp16 tensor
// cores, 1-pass. Base-2 fixed-reference softmax via ex2.approx.f16x2;
// l via P@ones MMA interleaved with PV. 64x128 M-split tiles for the two
// 128-CTA GEMMs (out-proj, ffn2). S=2048, D=1024, H=16, Dh=64, F=4096.
// ---------------------------------------------------------------------------

#define S_LEN 2048
#define DMODEL 1024
#define DFF 4096
#define NHEAD 16
#define HEADDIM 64

#define SD (S_LEN * DMODEL)
#define SF (S_LEN * DFF)

// fp32 intermediates: h0, ff, h
__device__ float g_scratch[3 * (size_t)SD];

// fp16 arena: weights (contiguous, cvt_multi order) + x_h + activations
__device__ __half g_fp16[40 * 1024 * 1024];

// concatenated biases: [0,3072) in-proj qkv, [3072,6144) out qkv
__device__ float g_bias[6144];

// ---------------------------------------------------------------------------
// helpers
// ---------------------------------------------------------------------------
__device__ __forceinline__ uint32_t smem_to_u32(const void* smem_ptr) {
    uint32_t addr;
    asm("{ .reg .u64 tmp; cvta.to.shared.u64 tmp, %1; cvt.u32.u64 %0, tmp; }"
        : "=r"(addr) : "l"(smem_ptr));
    return addr;
}

#define SW128(off) ((off) ^ (((off) >> 3) & 0x70))

__device__ __forceinline__ void cp_async16(uint32_t s, const void* g) {
    asm volatile("cp.async.cg.shared.global [%0], [%1], 16;" :: "r"(s), "l"(g));
}
#define CP_ASYNC_COMMIT() asm volatile("cp.async.commit_group;" ::: "memory")
#define CP_ASYNC_WAIT(n)  asm volatile("cp.async.wait_group %0;" :: "n"(n) : "memory")

__device__ __forceinline__ void ldsm_x4(uint32_t* r, uint32_t addr) {
    asm volatile("ldmatrix.sync.aligned.m8n8.x4.shared.b16 {%0,%1,%2,%3}, [%4];"
        : "=r"(r[0]), "=r"(r[1]), "=r"(r[2]), "=r"(r[3]) : "r"(addr));
}

__device__ __forceinline__ void ldsm_x4_t(uint32_t* r, uint32_t addr) {
    asm volatile("ldmatrix.sync.aligned.m8n8.x4.trans.shared.b16 {%0,%1,%2,%3}, [%4];"
        : "=r"(r[0]), "=r"(r[1]), "=r"(r[2]), "=r"(r[3]) : "r"(addr));
}

__device__ __forceinline__ void mma16816(float* c, const uint32_t* a,
                                         const uint32_t* b) {
    asm volatile(
        "mma.sync.aligned.m16n8k16.row.col.f32.f16.f16.f32 "
        "{%0,%1,%2,%3}, {%4,%5,%6,%7}, {%8,%9}, {%0,%1,%2,%3};"
        : "+f"(c[0]), "+f"(c[1]), "+f"(c[2]), "+f"(c[3])
        : "r"(a[0]), "r"(a[1]), "r"(a[2]), "r"(a[3]), "r"(b[0]), "r"(b[1]));
}

__device__ __forceinline__ uint32_t pack_f16x2(float lo, float hi) {
    uint32_t r;
    asm("cvt.rn.f16x2.f32 %0, %1, %2;" : "=r"(r) : "f"(hi), "f"(lo));
    return r;
}

// 2^x elementwise on packed fp16x2
__device__ __forceinline__ uint32_t h2ex2(uint32_t x) {
    uint32_t r;
    asm("ex2.approx.f16x2 %0, %1;" : "=r"(r) : "r"(x));
    return r;
}

// ---------------------------------------------------------------------------
// multi-segment fp32 -> fp16 conversion (9 weights + x), dst contiguous
// ---------------------------------------------------------------------------
struct CvtSrcs { const float* p[10]; };

#define CVT_TOTAL4 4456448

__global__ __launch_bounds__(256) void cvt_multi(CvtSrcs s, __half* dst) {
    const int i = blockIdx.x * 256 + threadIdx.x;
    if (i >= CVT_TOTAL4) return;
    const int cum[10] = {0, 262144, 524288, 786432, 1048576, 2097152,
                         3145728, 3407872, 3670016, 3932160};
    int seg = 0, bse = 0;
#pragma unroll
    for (int k = 1; k < 10; k++)
        if (i >= cum[k]) { seg = k; bse = cum[k]; }
    const float4 v = reinterpret_cast<const float4*>(s.p[seg])[i - bse];
    __half2* hp = reinterpret_cast<__half2*>(dst);
    hp[2 * i + 0] = __half2(__float2half(v.x), __float2half(v.y));
    hp[2 * i + 1] = __half2(__float2half(v.z), __float2half(v.w));
}

__global__ __launch_bounds__(256) void bias_cat_kernel(
    const float* a, const float* b, const float* c,
    const float* d, const float* e, const float* f, float* o)
{
    const int i = blockIdx.x * 256 + threadIdx.x;
    if (i >= 6144) return;
    const int sec = i >> 10, r = i & 1023;
    float v;
    switch (sec) {
        case 0: v = a[r]; break;
        case 1: v = b[r]; break;
        case 2: v = c[r]; break;
        case 3: v = d[r]; break;
        case 4: v = e[r]; break;
        default: v = f[r]; break;
    }
    o[i] = v;
}

// ---------------------------------------------------------------------------
// GEMM: C = A @ W^T + bias (opt ReLU), 1-pass fp16.
// 128x128 tile, BK=64, cp.async 3-stage (R12 ordering), occupancy 2.
// split3: remap output cols [0,3072) to 3 consecutive [S,1024] sections.
// scaleq: multiply cols [0,1024) by 0.125*log2(e) (Q pre-scale, base-2).
// ---------------------------------------------------------------------------
#define MAT_BYTES 16384              // 128 rows * 64 fp16 * 2B
#define STAGE_BYTES (2 * MAT_BYTES)  // Ah, Wh
#define GEMM_STAGES 3
#define GEMM_SMEM (GEMM_STAGES * STAGE_BYTES + 1024)

__global__ __launch_bounds__(256, 2) void gemm_tc(
    const __half* __restrict__ A, const __half* __restrict__ W,
    const float* __restrict__ bias, float* __restrict__ Cf,
    __half* __restrict__ Ch, int M, int N, int K, int relu,
    int split3, int scaleq)
{
    extern __shared__ char dsm[];
    const uint32_t raw = smem_to_u32(dsm);
    const uint32_t base = (raw + 1023u) & ~1023u;

    const int tid = threadIdx.x;
    const int lane = tid & 31;
    const int wid = tid >> 5;
    const int wm = (wid >> 2) * 64;
    const int wn = (wid & 3) * 32;
    const int m0 = blockIdx.y * 128;
    const int n0 = blockIdx.x * 128;

    uint32_t s_off[4];
    int g_row[4], g_col16[4];
#pragma unroll
    for (int it = 0; it < 4; it++) {
        const int v = tid + it * 256;
        const int r = v >> 3, cc = v & 7;
        s_off[it] = SW128((uint32_t)(r * 128 + cc * 16));
        g_row[it] = r;
        g_col16[it] = cc;
    }

    float acc[4][4][4];
#pragma unroll
    for (int i = 0; i < 4; i++)
#pragma unroll
        for (int j = 0; j < 4; j++)
#pragma unroll
            for (int q = 0; q < 4; q++) acc[i][j][q] = 0.f;

    uint32_t aRow[4];
#pragma unroll
    for (int mt = 0; mt < 4; mt++)
        aRow[mt] = (uint32_t)((wm + mt * 16 + (lane & 15)) * 128);
    const uint32_t aColHalf = (uint32_t)((lane >> 4) * 16);

    uint32_t bRow[2];
#pragma unroll
    for (int ntp = 0; ntp < 2; ntp++)
        bRow[ntp] = (uint32_t)((wn + ntp * 16 + ((lane >> 4) & 1) * 8 + (lane & 7)) * 128);
    const uint32_t bColHalf = (uint32_t)(((lane >> 3) & 1) * 16);

    const int nchunk = K >> 6;

    auto prefetch = [&](int c, int s) {
        const int k0 = c << 6;
        const uint32_t sb = base + (uint32_t)s * STAGE_BYTES;
#pragma unroll
        for (int it = 0; it < 4; it++) {
            const size_t ga = (size_t)(m0 + g_row[it]) * K + k0 + g_col16[it] * 8;
            const size_t gw = (size_t)(n0 + g_row[it]) * K + k0 + g_col16[it] * 8;
            cp_async16(sb + s_off[it],             A + ga);
            cp_async16(sb + MAT_BYTES + s_off[it], W + gw);
        }
        CP_ASYNC_COMMIT();
    };

    prefetch(0, 0);
    if (nchunk > 1) prefetch(1, 1);

    int sidx = 0;
    for (int c = 0; c < nchunk; c++) {
        const int s = sidx;
        sidx = (sidx + 1 == GEMM_STAGES) ? 0 : sidx + 1;
        if (c + 2 < nchunk) {
            prefetch(c + 2, (c + 2) % GEMM_STAGES);
            CP_ASYNC_WAIT(2);
        } else if (c + 1 < nchunk) {
            CP_ASYNC_WAIT(1);
        } else {
            CP_ASYNC_WAIT(0);
        }
        __syncthreads();

        const uint32_t sb = base + (uint32_t)s * STAGE_BYTES;
        const uint32_t sAh = sb;
        const uint32_t sWh = sb + MAT_BYTES;

#pragma unroll
        for (int kk = 0; kk < 4; kk++) {
            const uint32_t kOff = (uint32_t)(kk * 32);
            uint32_t ah[4][4];
#pragma unroll
            for (int mt = 0; mt < 4; mt++)
                ldsm_x4(ah[mt], sAh + SW128(aRow[mt] + kOff + aColHalf));
            uint32_t bh[2][4];
#pragma unroll
            for (int ntp = 0; ntp < 2; ntp++)
                ldsm_x4(bh[ntp], sWh + SW128(bRow[ntp] + kOff + bColHalf));
#pragma unroll
            for (int mt = 0; mt < 4; mt++)
#pragma unroll
                for (int nt = 0; nt < 4; nt++)
                    mma16816(acc[mt][nt], ah[mt], &bh[nt >> 1][(nt & 1) * 2]);
        }
        __syncthreads();
    }

    // epilogue
    float* Cf_eff = Cf;
    int n0e = n0, Nout = N;
    if (split3) {
        Cf_eff = Cf + (size_t)(n0 >> 10) * SD;
        n0e = n0 & 1023;
        Nout = 1024;
    }
    // base-2 softmax pre-scale: 1/8 * log2(e)
    const float qs = (scaleq && n0 < 1024) ? 0.18033688f : 1.0f;

    const int frow = lane >> 2;
    const int fcol = (lane & 3) * 2;
#pragma unroll
    for (int mt = 0; mt < 4; mt++) {
#pragma unroll
        for (int nt = 0; nt < 4; nt++) {
            const int bcol = n0 + wn + nt * 8 + fcol;
            const int col = n0e + wn + nt * 8 + fcol;
            const float b0 = bias[bcol], b1 = bias[bcol + 1];
            const int r0 = m0 + wm + mt * 16 + frow;
            float v00 = acc[mt][nt][0] + b0, v01 = acc[mt][nt][1] + b1;
            float v10 = acc[mt][nt][2] + b0, v11 = acc[mt][nt][3] + b1;
            if (relu) {
                v00 = fmaxf(v00, 0.f); v01 = fmaxf(v01, 0.f);
                v10 = fmaxf(v10, 0.f); v11 = fmaxf(v11, 0.f);
            }
            if (Cf) {
                float2 o0, o1;
                o0.x = v00; o0.y = v01; o1.x = v10; o1.y = v11;
                *reinterpret_cast<float2*>(Cf_eff + (size_t)r0 * Nout + col) = o0;
                *reinterpret_cast<float2*>(Cf_eff + (size_t)(r0 + 8) * Nout + col) = o1;
            }
            if (Ch) {
                *reinterpret_cast<__half2*>(Ch + (size_t)r0 * N + col + (n0 - n0e)) =
                    __half2(__float2half(v00 * qs), __float2half(v01 * qs));
                *reinterpret_cast<__half2*>(Ch + (size_t)(r0 + 8) * N + col + (n0 - n0e)) =
                    __half2(__float2half(v10 * qs), __float2half(v11 * qs));
            }
        }
    }
}

// ---------------------------------------------------------------------------
// GEMM64: C = A @ W^T + bias, fp32 out, no relu. 64x128 tile, BK=64,
// 8 warps as 2x4 of 32x32 warp tiles, 3-stage cp.async, occupancy 2.
// For the small-N GEMMs (out-proj, ffn2): doubles grid to 256 CTAs.
// ---------------------------------------------------------------------------
#define MAT64_A 8192                 // 64 rows * 128B
#define MAT64_W 16384                // 128 rows * 128B
#define STAGE64 (MAT64_A + MAT64_W)  // 24576
#define GEMM64_SMEM (3 * STAGE64 + 1024)

__global__ __launch_bounds__(256, 2) void gemm_tc64(
    const __half* __restrict__ A, const __half* __restrict__ W,
    const float* __restrict__ bias, float* __restrict__ Cf,
    int M, int N, int K)
{
    extern __shared__ char dsm[];
    const uint32_t raw = smem_to_u32(dsm);
    const uint32_t base = (raw + 1023u) & ~1023u;

    const int tid = threadIdx.x;
    const int lane = tid & 31;
    const int wid = tid >> 5;
    const int wm = (wid >> 2) * 32;      // 2 m-groups of 32 rows
    const int wn = (wid & 3) * 32;       // 4 n-groups of 32 cols
    const int m0 = blockIdx.y * 64;
    const int n0 = blockIdx.x * 128;

    // A loader: 512 16B-vectors (2 per thread); W loader: 1024 (4 per thread)
    uint32_t sa_off[2];
    int ga_row[2], ga_c16[2];
#pragma unroll
    for (int it = 0; it < 2; it++) {
        const int v = tid + it * 256;
        ga_row[it] = v >> 3; ga_c16[it] = v & 7;
        sa_off[it] = SW128((uint32_t)(ga_row[it] * 128 + ga_c16[it] * 16));
    }
    uint32_t sw_off[4];
    int gw_row[4], gw_c16[4];
#pragma unroll
    for (int it = 0; it < 4; it++) {
        const int v = tid + it * 256;
        gw_row[it] = v >> 3; gw_c16[it] = v & 7;
        sw_off[it] = SW128((uint32_t)(gw_row[it] * 128 + gw_c16[it] * 16));
    }

    float acc[2][4][4];
#pragma unroll
    for (int i = 0; i < 2; i++)
#pragma unroll
        for (int j = 0; j < 4; j++)
#pragma unroll
            for (int q = 0; q < 4; q++) acc[i][j][q] = 0.f;

    uint32_t aRow[2];
#pragma unroll
    for (int mt = 0; mt < 2; mt++)
        aRow[mt] = (uint32_t)((wm + mt * 16 + (lane & 15)) * 128);
    const uint32_t aColHalf = (uint32_t)((lane >> 4) * 16);

    uint32_t bRow[2];
#pragma unroll
    for (int ntp = 0; ntp < 2; ntp++)
        bRow[ntp] = (uint32_t)((wn + ntp * 16 + ((lane >> 4) & 1) * 8 + (lane & 7)) * 128);
    const uint32_t bColHalf = (uint32_t)(((lane >> 3) & 1) * 16);

    const int nchunk = K >> 6;

    auto prefetch = [&](int c, int s) {
        const int k0 = c << 6;
        const uint32_t sb = base + (uint32_t)s * STAGE64;
#pragma unroll
        for (int it = 0; it < 2; it++) {
            const size_t ga = (size_t)(m0 + ga_row[it]) * K + k0 + ga_c16[it] * 8;
            cp_async16(sb + sa_off[it], A + ga);
        }
#pragma unroll
        for (int it = 0; it < 4; it++) {
            const size_t gw = (size_t)(n0 + gw_row[it]) * K + k0 + gw_c16[it] * 8;
            cp_async16(sb + MAT64_A + sw_off[it], W + gw);
        }
        CP_ASYNC_COMMIT();
    };

    prefetch(0, 0);
    if (nchunk > 1) prefetch(1, 1);

    int sidx = 0;
    for (int c = 0; c < nchunk; c++) {
        const int s = sidx;
        sidx = (sidx + 1 == 3) ? 0 : sidx + 1;
        if (c + 2 < nchunk) {
            prefetch(c + 2, (c + 2) % 3);
            CP_ASYNC_WAIT(2);
        } else if (c + 1 < nchunk) {
            CP_ASYNC_WAIT(1);
        } else {
            CP_ASYNC_WAIT(0);
        }
        __syncthreads();

        const uint32_t sb = base + (uint32_t)s * STAGE64;
        const uint32_t sAh = sb;
        const uint32_t sWh = sb + MAT64_A;

#pragma unroll
        for (int kk = 0; kk < 4; kk++) {
            const uint32_t kOff = (uint32_t)(kk * 32);
            uint32_t ah[2][4];
#pragma unroll
            for (int mt = 0; mt < 2; mt++)
                ldsm_x4(ah[mt], sAh + SW128(aRow[mt] + kOff + aColHalf));
            uint32_t bh[2][4];
#pragma unroll
            for (int ntp = 0; ntp < 2; ntp++)
                ldsm_x4(bh[ntp], sWh + SW128(bRow[ntp] + kOff + bColHalf));
#pragma unroll
            for (int mt = 0; mt < 2; mt++)
#pragma unroll
                for (int nt = 0; nt < 4; nt++)
                    mma16816(acc[mt][nt], ah[mt], &bh[nt >> 1][(nt & 1) * 2]);
        }
        __syncthreads();
    }

    const int frow = lane >> 2;
    const int fcol = (lane & 3) * 2;
#pragma unroll
    for (int mt = 0; mt < 2; mt++) {
#pragma unroll
        for (int nt = 0; nt < 4; nt++) {
            const int col = n0 + wn + nt * 8 + fcol;
            const float b0 = bias[col], b1 = bias[col + 1];
            const int r0 = m0 + wm + mt * 16 + frow;
            float2 o0, o1;
            o0.x = acc[mt][nt][0] + b0; o0.y = acc[mt][nt][1] + b1;
            o1.x = acc[mt][nt][2] + b0; o1.y = acc[mt][nt][3] + b1;
            *reinterpret_cast<float2*>(Cf + (size_t)r0 * N + col) = o0;
            *reinterpret_cast<float2*>(Cf + (size_t)(r0 + 8) * N + col) = o1;
        }
    }
}

// ---------------------------------------------------------------------------
// Attention (FA2-style fp16, R12 config). QKV packed [S, 3072], Q pre-scaled
// by 0.125*log2e. Base-2 fixed-reference softmax via ex2.approx.f16x2.
// l via P@ones MMA interleaved into the PV loop.
// 128 queries x 1 head / block, 256 thr, K-tile 64, 2-stage.
// ---------------------------------------------------------------------------
#define QKV_LD 3072
#define ATT_QBYTES 16384             // 128 x 64 fp16
#define ATT_KBYTES 8192              // 64 x 64 fp16
#define ATT_STAGE  (2 * ATT_KBYTES)  // Kh, Vh
#define ATT_SMEM   (ATT_QBYTES + 2 * ATT_STAGE + 1024)

__global__ __launch_bounds__(256, 2) void attn_tc(
    const __half* __restrict__ QKV, __half* __restrict__ Oh)
{
    extern __shared__ char dsm[];
    const uint32_t raw = smem_to_u32(dsm);
    const uint32_t base = (raw + 1023u) & ~1023u;
    const uint32_t uQH = base;
    const uint32_t uST = base + ATT_QBYTES;

    const int tid = threadIdx.x;
    const int lane = tid & 31;
    const int wid = tid >> 5;
    const int head = blockIdx.y;
    const int q0 = blockIdx.x * 128;
    const int hcol = head * HEADDIM;

    // ---- load Q tile (group 0) ----
#pragma unroll
    for (int it = 0; it < 4; it++) {
        const int v = tid + it * 256;
        const int r = v >> 3, c16 = v & 7;
        const size_t g = (size_t)(q0 + r) * QKV_LD + hcol + c16 * 8;
        cp_async16(uQH + SW128((uint32_t)(r * 128 + c16 * 16)), QKV + g);
    }
    CP_ASYNC_COMMIT();

    auto kvload = [&](int t, int s) {
        const int kb = t * 64;
        const uint32_t uS = uST + (uint32_t)s * ATT_STAGE;
#pragma unroll
        for (int it = 0; it < 2; it++) {
            const int v = tid + it * 256;
            const int r = v >> 3, c16 = v & 7;
            const size_t gk = (size_t)(kb + r) * QKV_LD + 1024 + hcol + c16 * 8;
            const size_t gv = (size_t)(kb + r) * QKV_LD + 2048 + hcol + c16 * 8;
            const uint32_t sw = SW128((uint32_t)(r * 128 + c16 * 16));
            cp_async16(uS + sw,              QKV + gk);
            cp_async16(uS + ATT_KBYTES + sw, QKV + gv);
        }
        CP_ASYNC_COMMIT();
    };

    kvload(0, 0);   // group 1

    const uint32_t aRow = (uint32_t)((wid * 16 + (lane & 15)) * 128);
    const uint32_t aHalf = (uint32_t)((lane >> 4) * 16);
    uint32_t bRow[4];
#pragma unroll
    for (int ntp = 0; ntp < 4; ntp++)
        bRow[ntp] = (uint32_t)((ntp * 16 + ((lane >> 4) & 1) * 8 + (lane & 7)) * 128);
    const uint32_t bHalf = (uint32_t)(((lane >> 3) & 1) * 16);
    const uint32_t vRowPart = (uint32_t)((lane & 15) * 128);
    const uint32_t vColPart = (uint32_t)((lane >> 4) * 16);

    // ---- hoist Q fragments (loop-invariant) ----
    CP_ASYNC_WAIT(1);            // group 0 (Q) complete
    __syncthreads();
    uint32_t aq[4][4];
#pragma unroll
    for (int kk = 0; kk < 4; kk++)
        ldsm_x4(aq[kk], uQH + SW128(aRow + (uint32_t)(kk * 32) + aHalf));

    float oacc[8][4];
#pragma unroll
    for (int i = 0; i < 8; i++)
#pragma unroll
        for (int q = 0; q < 4; q++) oacc[i][q] = 0.f;
    float lacc[4] = {0.f, 0.f, 0.f, 0.f};
    const uint32_t onesh2 = 0x3C003C00u;          // (1.0h, 1.0h)
    const uint32_t bOnes[2] = {onesh2, onesh2};

    const int ntiles = S_LEN / 64;
    for (int t = 0; t < ntiles; t++) {
        const int s = t & 1;
        if (t + 1 < ntiles) {
            kvload(t + 1, s ^ 1);   // issue BEFORE wait
            CP_ASYNC_WAIT(1);
        } else {
            CP_ASYNC_WAIT(0);
        }
        __syncthreads();

        const uint32_t uS = uST + (uint32_t)s * ATT_STAGE;
        const uint32_t uKH = uS;
        const uint32_t uVH = uS + ATT_KBYTES;

        // ---- S = Q K^T (Q pre-scaled; result in log2 domain) ----
        float sacc[8][4];
#pragma unroll
        for (int i = 0; i < 8; i++)
#pragma unroll
            for (int q = 0; q < 4; q++) sacc[i][q] = 0.f;

#pragma unroll
        for (int kk = 0; kk < 4; kk++) {
            const uint32_t kOff = (uint32_t)(kk * 32);
#pragma unroll
            for (int ntp = 0; ntp < 4; ntp++) {
                uint32_t bh[4];
                ldsm_x4(bh, uKH + SW128(bRow[ntp] + kOff + bHalf));
                mma16816(sacc[2 * ntp],     aq[kk], &bh[0]);
                mma16816(sacc[2 * ntp + 1], aq[kk], &bh[2]);
            }
        }

        // ---- p = 2^s in fp16x2 ----
        uint32_t aP[4][4];
#pragma unroll
        for (int kc = 0; kc < 4; kc++) {
            const int ne = 2 * kc, no = 2 * kc + 1;
            aP[kc][0] = h2ex2(pack_f16x2(sacc[ne][0], sacc[ne][1]));
            aP[kc][1] = h2ex2(pack_f16x2(sacc[ne][2], sacc[ne][3]));
            aP[kc][2] = h2ex2(pack_f16x2(sacc[no][0], sacc[no][1]));
            aP[kc][3] = h2ex2(pack_f16x2(sacc[no][2], sacc[no][3]));
        }

        // ---- O += P V ; l += P @ ones (interleaved) ----
#pragma unroll
        for (int kc = 0; kc < 4; kc++) {
            const uint32_t kRow = (uint32_t)(kc * 16 * 128);
            mma16816(lacc, aP[kc], bOnes);
#pragma unroll
            for (int ntp = 0; ntp < 4; ntp++) {
                uint32_t vb[4];
                ldsm_x4_t(vb, uVH +
                    SW128(kRow + vRowPart + (uint32_t)(ntp * 32) + vColPart));
                mma16816(oacc[2 * ntp],     aP[kc], &vb[0]);
                mma16816(oacc[2 * ntp + 1], aP[kc], &vb[2]);
            }
        }
        __syncthreads();
    }

    // finalize: lacc[0]/lacc[2] hold the row sums (all B-cols equal)
    const float inv0 = 1.f / lacc[0];
    const float inv1 = 1.f / lacc[2];

    const int row0 = q0 + wid * 16 + (lane >> 2);
    const int row1 = row0 + 8;
    const int cbase = hcol + (lane & 3) * 2;
#pragma unroll
    for (int nt = 0; nt < 8; nt++) {
        const int col = cbase + nt * 8;
        *reinterpret_cast<__half2*>(Oh + (size_t)row0 * DMODEL + col) =
            __half2(__float2half(oacc[nt][0] * inv0),
                    __float2half(oacc[nt][1] * inv0));
        *reinterpret_cast<__half2*>(Oh + (size_t)row1 * DMODEL + col) =
            __half2(__float2half(oacc[nt][2] * inv1),
                    __float2half(oacc[nt][3] * inv1));
    }
}

// ---------------------------------------------------------------------------
// add + LayerNorm; fp32 + fp16 hi outputs
// ---------------------------------------------------------------------------
__global__ __launch_bounds__(256) void add_ln_kernel(
    const float* __restrict__ a, const float* __restrict__ b,
    const float* __restrict__ gamma, const float* __restrict__ beta,
    float* __restrict__ out, __half* __restrict__ oh)
{
    const int row = blockIdx.x;
    const int tid = threadIdx.x;
    const int c = tid * 4;

    const float4 va = *reinterpret_cast<const float4*>(&a[(size_t)row * DMODEL + c]);
    const float4 vb = *reinterpret_cast<const float4*>(&b[(size_t)row * DMODEL + c]);
    float v0 = va.x + vb.x, v1 = va.y + vb.y, v2 = va.z + vb.z, v3 = va.w + vb.w;

    float s = v0 + v1 + v2 + v3;
    float sq = v0 * v0 + v1 * v1 + v2 * v2 + v3 * v3;
#pragma unroll
    for (int o = 16; o > 0; o >>= 1) {
        s += __shfl_xor_sync(0xffffffffu, s, o);
        sq += __shfl_xor_sync(0xffffffffu, sq, o);
    }

    __shared__ float sh_s[8], sh_sq[8], sh_mean, sh_r;
    const int warp = tid >> 5, lane = tid & 31;
    if (lane == 0) { sh_s[warp] = s; sh_sq[warp] = sq; }
    __syncthreads();
    if (tid == 0) {
        float ts = 0.f, tq = 0.f;
#pragma unroll
        for (int i = 0; i < 8; i++) { ts += sh_s[i]; tq += sh_sq[i]; }
        const float mean = ts * (1.f / DMODEL);
        const float var = tq * (1.f / DMODEL) - mean * mean;
        sh_mean = mean;
        sh_r = rsqrtf(var + 1e-5f);
    }
    __syncthreads();
    const float mean = sh_mean, r = sh_r;

    const float4 g4 = *reinterpret_cast<const float4*>(&gamma[c]);
    const float4 b4 = *reinterpret_cast<const float4*>(&beta[c]);
    float4 o4;
    o4.x = (v0 - mean) * r * g4.x + b4.x;
    o4.y = (v1 - mean) * r * g4.y + b4.y;
    o4.z = (v2 - mean) * r * g4.z + b4.z;
    o4.w = (v3 - mean) * r * g4.w + b4.w;
    *reinterpret_cast<float4*>(&out[(size_t)row * DMODEL + c]) = o4;

    __half2* hp = reinterpret_cast<__half2*>(oh + (size_t)row * DMODEL + c);
    hp[0] = __half2(__float2half(o4.x), __float2half(o4.y));
    hp[1] = __half2(__float2half(o4.z), __float2half(o4.w));
}

// ---------------------------------------------------------------------------
// Launch
// ---------------------------------------------------------------------------
extern "C" void kernel_launch(void* const* d_in, const int* in_sizes, int n_in,
                              void* d_out, int out_size)
{
    const float* x      = (const float*)d_in[0];
    const float* q_in_w = (const float*)d_in[1];
    const float* q_in_b = (const float*)d_in[2];
    const float* k_in_w = (const float*)d_in[3];
    const float* k_in_b = (const float*)d_in[4];
    const float* v_in_w = (const float*)d_in[5];
    const float* v_in_b = (const float*)d_in[6];
    const float* out_w  = (const float*)d_in[7];
    const float* out_b  = (const float*)d_in[8];
    const float* ffn1_w = (const float*)d_in[9];
    const float* ffn1_b = (const float*)d_in[10];
    const float* ffn2_w = (const float*)d_in[11];
    const float* ffn2_b = (const float*)d_in[12];
    const float* n1_g   = (const float*)d_in[13];
    const float* n1_b   = (const float*)d_in[14];
    const float* n2_g   = (const float*)d_in[15];
    const float* n2_b   = (const float*)d_in[16];
    const float* q_out_w = (const float*)d_in[17];
    const float* q_out_b = (const float*)d_in[18];
    const float* k_out_w = (const float*)d_in[19];
    const float* k_out_b = (const float*)d_in[20];
    const float* v_out_w = (const float*)d_in[21];
    const float* v_out_b = (const float*)d_in[22];

    float* out = (float*)d_out;

    cudaFuncSetAttribute(gemm_tc, cudaFuncAttributeMaxDynamicSharedMemorySize,
                         GEMM_SMEM);
    cudaFuncSetAttribute(gemm_tc64, cudaFuncAttributeMaxDynamicSharedMemorySize,
                         GEMM64_SMEM);
    cudaFuncSetAttribute(attn_tc, cudaFuncAttributeMaxDynamicSharedMemorySize,
                         ATT_SMEM);

    float* scratch = nullptr;
    cudaGetSymbolAddress((void**)&scratch, g_scratch);
    float* h0 = scratch + 0 * (size_t)SD;
    float* ff = scratch + 1 * (size_t)SD;
    float* h  = scratch + 2 * (size_t)SD;

    float* bias_cat = nullptr;
    cudaGetSymbolAddress((void**)&bias_cat, g_bias);

    float* y = out + 3 * (size_t)SD;

    __half* fp = nullptr;
    cudaGetSymbolAddress((void**)&fp, g_fp16);
    size_t off = 0;
    auto take1 = [&](size_t n) { __half* p = fp + off; off += n; return p; };

    // weights (contiguous, cvt_multi segment order), then x_h
    __half* qiw = take1((size_t)DMODEL * DMODEL);
    __half* kiw = take1((size_t)DMODEL * DMODEL);
    __half* viw = take1((size_t)DMODEL * DMODEL);
    __half* ow  = take1((size_t)DMODEL * DMODEL);
    __half* f1w = take1((size_t)DMODEL * DFF);
    __half* f2w = take1((size_t)DFF * DMODEL);
    __half* qow = take1((size_t)DMODEL * DMODEL);
    __half* kow = take1((size_t)DMODEL * DMODEL);
    __half* vow = take1((size_t)DMODEL * DMODEL);
    __half* x_h = take1(SD);
    // activations
    __half* qkv_h  = take1((size_t)S_LEN * 3072);
    __half* attn_h = take1(SD);
    __half* h_h    = take1(SD);
    __half* ff1_h  = take1(SF);
    __half* y_h    = take1(SD);
    (void)kiw; (void)viw; (void)kow; (void)vow;

    // conversions: one multi-segment kernel
    CvtSrcs srcs;
    srcs.p[0] = q_in_w;  srcs.p[1] = k_in_w;  srcs.p[2] = v_in_w;
    srcs.p[3] = out_w;   srcs.p[4] = ffn1_w;  srcs.p[5] = ffn2_w;
    srcs.p[6] = q_out_w; srcs.p[7] = k_out_w; srcs.p[8] = v_out_w;
    srcs.p[9] = x;
    cvt_multi<<<(CVT_TOTAL4 + 255) / 256, 256>>>(srcs, qiw);

    bias_cat_kernel<<<24, 256>>>(q_in_b, k_in_b, v_in_b,
                                 q_out_b, k_out_b, v_out_b, bias_cat);

    const dim3 g3(3072 / 128, S_LEN / 128);   // merged qkv / final
    const dim3 g64(DMODEL / 128, S_LEN / 64); // 64-row tiles: 8 x 32 = 256 CTAs
    const dim3 gF(DFF / 128, S_LEN / 128);

    // merged in-projection -> qkv_h [S, 3072]; Q cols pre-scaled (base-2)
    gemm_tc<<<g3, 256, GEMM_SMEM>>>(x_h, qiw, bias_cat,
                                    nullptr, qkv_h, S_LEN, 3072, DMODEL, 0, 0, 1);

    // attention -> attn_h
    attn_tc<<<dim3(S_LEN / 128, NHEAD), 256, ATT_SMEM>>>(qkv_h, attn_h);

    // out-proj (64-row tiles, 256 CTAs) + LN1
    gemm_tc64<<<g64, 256, GEMM64_SMEM>>>(attn_h, ow, out_b, h0,
                                         S_LEN, DMODEL, DMODEL);
    add_ln_kernel<<<S_LEN, 256>>>(x, h0, n1_g, n1_b, h, h_h);

    // FFN + LN2 (ffn2 on 64-row tiles, 256 CTAs)
    gemm_tc<<<gF, 256, GEMM_SMEM>>>(h_h, f1w, ffn1_b,
                                    nullptr, ff1_h, S_LEN, DFF, DMODEL, 1, 0, 0);
    gemm_tc64<<<g64, 256, GEMM64_SMEM>>>(ff1_h, f2w, ffn2_b, ff,
                                         S_LEN, DMODEL, DFF);
    add_ln_kernel<<<S_LEN, 256>>>(h, ff, n2_g, n2_b, y, y_h);

    // merged next-layer projections -> out[0..3*SD) via split3 remap
    gemm_tc<<<g3, 256, GEMM_SMEM>>>(y_h, qow, bias_cat + 3072,
                                    out, nullptr, S_LEN, 3072, DMODEL, 0, 1, 0);
}

// round 17
// speedup vs baseline: 1.0265x; 1.0265x over previous
#include <cuda_runtime.h>
#include <cuda_fp16.h>
#include <cstdint>
#include <math.h>

// ---------------------------------------------------------------------------
// Transformer encoder layer. All GEMMs + attention on mma.sync fp16 tensor
// cores, 1-pass. Base-2 fixed-reference softmax via ex2.approx.f16x2;
// l via P@ones MMA interleaved with PV. R12 configuration (best measured).
// S=2048, D=1024, H=16, Dh=64, F=4096.
// ---------------------------------------------------------------------------

#define S_LEN 2048
#define DMODEL 1024
#define DFF 4096
#define NHEAD 16
#define HEADDIM 64

#define SD (S_LEN * DMODEL)
#define SF (S_LEN * DFF)

// fp32 intermediates: h0, ff, h
__device__ float g_scratch[3 * (size_t)SD];

// fp16 arena: weights (contiguous, cvt_multi order) + x_h + activations
__device__ __half g_fp16[40 * 1024 * 1024];

// concatenated biases: [0,3072) in-proj qkv, [3072,6144) out qkv
__device__ float g_bias[6144];

// ---------------------------------------------------------------------------
// helpers
// ---------------------------------------------------------------------------
__device__ __forceinline__ uint32_t smem_to_u32(const void* smem_ptr) {
    uint32_t addr;
    asm("{ .reg .u64 tmp; cvta.to.shared.u64 tmp, %1; cvt.u32.u64 %0, tmp; }"
        : "=r"(addr) : "l"(smem_ptr));
    return addr;
}

#define SW128(off) ((off) ^ (((off) >> 3) & 0x70))

__device__ __forceinline__ void cp_async16(uint32_t s, const void* g) {
    asm volatile("cp.async.cg.shared.global [%0], [%1], 16;" :: "r"(s), "l"(g));
}
#define CP_ASYNC_COMMIT() asm volatile("cp.async.commit_group;" ::: "memory")
#define CP_ASYNC_WAIT(n)  asm volatile("cp.async.wait_group %0;" :: "n"(n) : "memory")

__device__ __forceinline__ void ldsm_x4(uint32_t* r, uint32_t addr) {
    asm volatile("ldmatrix.sync.aligned.m8n8.x4.shared.b16 {%0,%1,%2,%3}, [%4];"
        : "=r"(r[0]), "=r"(r[1]), "=r"(r[2]), "=r"(r[3]) : "r"(addr));
}

__device__ __forceinline__ void ldsm_x4_t(uint32_t* r, uint32_t addr) {
    asm volatile("ldmatrix.sync.aligned.m8n8.x4.trans.shared.b16 {%0,%1,%2,%3}, [%4];"
        : "=r"(r[0]), "=r"(r[1]), "=r"(r[2]), "=r"(r[3]) : "r"(addr));
}

__device__ __forceinline__ void mma16816(float* c, const uint32_t* a,
                                         const uint32_t* b) {
    asm volatile(
        "mma.sync.aligned.m16n8k16.row.col.f32.f16.f16.f32 "
        "{%0,%1,%2,%3}, {%4,%5,%6,%7}, {%8,%9}, {%0,%1,%2,%3};"
        : "+f"(c[0]), "+f"(c[1]), "+f"(c[2]), "+f"(c[3])
        : "r"(a[0]), "r"(a[1]), "r"(a[2]), "r"(a[3]), "r"(b[0]), "r"(b[1]));
}

__device__ __forceinline__ uint32_t pack_f16x2(float lo, float hi) {
    uint32_t r;
    asm("cvt.rn.f16x2.f32 %0, %1, %2;" : "=r"(r) : "f"(hi), "f"(lo));
    return r;
}

// 2^x elementwise on packed fp16x2
__device__ __forceinline__ uint32_t h2ex2(uint32_t x) {
    uint32_t r;
    asm("ex2.approx.f16x2 %0, %1;" : "=r"(r) : "r"(x));
    return r;
}

// ---------------------------------------------------------------------------
// multi-segment fp32 -> fp16 conversion (9 weights + x), dst contiguous
// ---------------------------------------------------------------------------
struct CvtSrcs { const float* p[10]; };

#define CVT_TOTAL4 4456448

__global__ __launch_bounds__(256) void cvt_multi(CvtSrcs s, __half* dst) {
    const int i = blockIdx.x * 256 + threadIdx.x;
    if (i >= CVT_TOTAL4) return;
    const int cum[10] = {0, 262144, 524288, 786432, 1048576, 2097152,
                         3145728, 3407872, 3670016, 3932160};
    int seg = 0, bse = 0;
#pragma unroll
    for (int k = 1; k < 10; k++)
        if (i >= cum[k]) { seg = k; bse = cum[k]; }
    const float4 v = reinterpret_cast<const float4*>(s.p[seg])[i - bse];
    __half2* hp = reinterpret_cast<__half2*>(dst);
    hp[2 * i + 0] = __half2(__float2half(v.x), __float2half(v.y));
    hp[2 * i + 1] = __half2(__float2half(v.z), __float2half(v.w));
}

__global__ __launch_bounds__(256) void bias_cat_kernel(
    const float* a, const float* b, const float* c,
    const float* d, const float* e, const float* f, float* o)
{
    const int i = blockIdx.x * 256 + threadIdx.x;
    if (i >= 6144) return;
    const int sec = i >> 10, r = i & 1023;
    float v;
    switch (sec) {
        case 0: v = a[r]; break;
        case 1: v = b[r]; break;
        case 2: v = c[r]; break;
        case 3: v = d[r]; break;
        case 4: v = e[r]; break;
        default: v = f[r]; break;
    }
    o[i] = v;
}

// ---------------------------------------------------------------------------
// GEMM: C = A @ W^T + bias (opt ReLU), 1-pass fp16.
// 128x128 tile, BK=64, cp.async 3-stage (prefetch before wait), occupancy 2.
// split3: remap output cols [0,3072) to 3 consecutive [S,1024] sections.
// scaleq: multiply cols [0,1024) by 0.125*log2(e) (Q pre-scale, base-2).
// ---------------------------------------------------------------------------
#define MAT_BYTES 16384              // 128 rows * 64 fp16 * 2B
#define STAGE_BYTES (2 * MAT_BYTES)  // Ah, Wh
#define GEMM_STAGES 3
#define GEMM_SMEM (GEMM_STAGES * STAGE_BYTES + 1024)

__global__ __launch_bounds__(256, 2) void gemm_tc(
    const __half* __restrict__ A, const __half* __restrict__ W,
    const float* __restrict__ bias, float* __restrict__ Cf,
    __half* __restrict__ Ch, int M, int N, int K, int relu,
    int split3, int scaleq)
{
    extern __shared__ char dsm[];
    const uint32_t raw = smem_to_u32(dsm);
    const uint32_t base = (raw + 1023u) & ~1023u;

    const int tid = threadIdx.x;
    const int lane = tid & 31;
    const int wid = tid >> 5;
    const int wm = (wid >> 2) * 64;
    const int wn = (wid & 3) * 32;
    const int m0 = blockIdx.y * 128;
    const int n0 = blockIdx.x * 128;

    uint32_t s_off[4];
    int g_row[4], g_col16[4];
#pragma unroll
    for (int it = 0; it < 4; it++) {
        const int v = tid + it * 256;
        const int r = v >> 3, cc = v & 7;
        s_off[it] = SW128((uint32_t)(r * 128 + cc * 16));
        g_row[it] = r;
        g_col16[it] = cc;
    }

    float acc[4][4][4];
#pragma unroll
    for (int i = 0; i < 4; i++)
#pragma unroll
        for (int j = 0; j < 4; j++)
#pragma unroll
            for (int q = 0; q < 4; q++) acc[i][j][q] = 0.f;

    uint32_t aRow[4];
#pragma unroll
    for (int mt = 0; mt < 4; mt++)
        aRow[mt] = (uint32_t)((wm + mt * 16 + (lane & 15)) * 128);
    const uint32_t aColHalf = (uint32_t)((lane >> 4) * 16);

    uint32_t bRow[2];
#pragma unroll
    for (int ntp = 0; ntp < 2; ntp++)
        bRow[ntp] = (uint32_t)((wn + ntp * 16 + ((lane >> 4) & 1) * 8 + (lane & 7)) * 128);
    const uint32_t bColHalf = (uint32_t)(((lane >> 3) & 1) * 16);

    const int nchunk = K >> 6;

    auto prefetch = [&](int c, int s) {
        const int k0 = c << 6;
        const uint32_t sb = base + (uint32_t)s * STAGE_BYTES;
#pragma unroll
        for (int it = 0; it < 4; it++) {
            const size_t ga = (size_t)(m0 + g_row[it]) * K + k0 + g_col16[it] * 8;
            const size_t gw = (size_t)(n0 + g_row[it]) * K + k0 + g_col16[it] * 8;
            cp_async16(sb + s_off[it],             A + ga);
            cp_async16(sb + MAT_BYTES + s_off[it], W + gw);
        }
        CP_ASYNC_COMMIT();
    };

    prefetch(0, 0);
    if (nchunk > 1) prefetch(1, 1);

    int sidx = 0;
    for (int c = 0; c < nchunk; c++) {
        const int s = sidx;
        sidx = (sidx + 1 == GEMM_STAGES) ? 0 : sidx + 1;
        if (c + 2 < nchunk) {
            prefetch(c + 2, (c + 2) % GEMM_STAGES);
            CP_ASYNC_WAIT(2);
        } else if (c + 1 < nchunk) {
            CP_ASYNC_WAIT(1);
        } else {
            CP_ASYNC_WAIT(0);
        }
        __syncthreads();

        const uint32_t sb = base + (uint32_t)s * STAGE_BYTES;
        const uint32_t sAh = sb;
        const uint32_t sWh = sb + MAT_BYTES;

#pragma unroll
        for (int kk = 0; kk < 4; kk++) {
            const uint32_t kOff = (uint32_t)(kk * 32);
            uint32_t ah[4][4];
#pragma unroll
            for (int mt = 0; mt < 4; mt++)
                ldsm_x4(ah[mt], sAh + SW128(aRow[mt] + kOff + aColHalf));
            uint32_t bh[2][4];
#pragma unroll
            for (int ntp = 0; ntp < 2; ntp++)
                ldsm_x4(bh[ntp], sWh + SW128(bRow[ntp] + kOff + bColHalf));
#pragma unroll
            for (int mt = 0; mt < 4; mt++)
#pragma unroll
                for (int nt = 0; nt < 4; nt++)
                    mma16816(acc[mt][nt], ah[mt], &bh[nt >> 1][(nt & 1) * 2]);
        }
        __syncthreads();
    }

    // epilogue
    float* Cf_eff = Cf;
    int n0e = n0, Nout = N;
    if (split3) {
        Cf_eff = Cf + (size_t)(n0 >> 10) * SD;
        n0e = n0 & 1023;
        Nout = 1024;
    }
    // base-2 softmax pre-scale: 1/8 * log2(e)
    const float qs = (scaleq && n0 < 1024) ? 0.18033688f : 1.0f;

    const int frow = lane >> 2;
    const int fcol = (lane & 3) * 2;
#pragma unroll
    for (int mt = 0; mt < 4; mt++) {
#pragma unroll
        for (int nt = 0; nt < 4; nt++) {
            const int bcol = n0 + wn + nt * 8 + fcol;
            const int col = n0e + wn + nt * 8 + fcol;
            const float b0 = bias[bcol], b1 = bias[bcol + 1];
            const int r0 = m0 + wm + mt * 16 + frow;
            float v00 = acc[mt][nt][0] + b0, v01 = acc[mt][nt][1] + b1;
            float v10 = acc[mt][nt][2] + b0, v11 = acc[mt][nt][3] + b1;
            if (relu) {
                v00 = fmaxf(v00, 0.f); v01 = fmaxf(v01, 0.f);
                v10 = fmaxf(v10, 0.f); v11 = fmaxf(v11, 0.f);
            }
            if (Cf) {
                float2 o0, o1;
                o0.x = v00; o0.y = v01; o1.x = v10; o1.y = v11;
                *reinterpret_cast<float2*>(Cf_eff + (size_t)r0 * Nout + col) = o0;
                *reinterpret_cast<float2*>(Cf_eff + (size_t)(r0 + 8) * Nout + col) = o1;
            }
            if (Ch) {
                *reinterpret_cast<__half2*>(Ch + (size_t)r0 * N + col + (n0 - n0e)) =
                    __half2(__float2half(v00 * qs), __float2half(v01 * qs));
                *reinterpret_cast<__half2*>(Ch + (size_t)(r0 + 8) * N + col + (n0 - n0e)) =
                    __half2(__float2half(v10 * qs), __float2half(v11 * qs));
            }
        }
    }
}

// ---------------------------------------------------------------------------
// Attention (FA2-style fp16). QKV packed [S, 3072], Q pre-scaled by
// 0.125*log2e. Base-2 fixed-reference softmax: p = 2^s via ex2.approx.f16x2.
// l via P@ones MMA interleaved into the PV loop.
// 128 queries x 1 head / block, 256 thr, K-tile 64, 2-stage.
// ---------------------------------------------------------------------------
#define QKV_LD 3072
#define ATT_QBYTES 16384             // 128 x 64 fp16
#define ATT_KBYTES 8192              // 64 x 64 fp16
#define ATT_STAGE  (2 * ATT_KBYTES)  // Kh, Vh
#define ATT_SMEM   (ATT_QBYTES + 2 * ATT_STAGE + 1024)

__global__ __launch_bounds__(256, 2) void attn_tc(
    const __half* __restrict__ QKV, __half* __restrict__ Oh)
{
    extern __shared__ char dsm[];
    const uint32_t raw = smem_to_u32(dsm);
    const uint32_t base = (raw + 1023u) & ~1023u;
    const uint32_t uQH = base;
    const uint32_t uST = base + ATT_QBYTES;

    const int tid = threadIdx.x;
    const int lane = tid & 31;
    const int wid = tid >> 5;
    const int head = blockIdx.y;
    const int q0 = blockIdx.x * 128;
    const int hcol = head * HEADDIM;

    // ---- load Q tile (group 0) ----
#pragma unroll
    for (int it = 0; it < 4; it++) {
        const int v = tid + it * 256;
        const int r = v >> 3, c16 = v & 7;
        const size_t g = (size_t)(q0 + r) * QKV_LD + hcol + c16 * 8;
        cp_async16(uQH + SW128((uint32_t)(r * 128 + c16 * 16)), QKV + g);
    }
    CP_ASYNC_COMMIT();

    auto kvload = [&](int t, int s) {
        const int kb = t * 64;
        const uint32_t uS = uST + (uint32_t)s * ATT_STAGE;
#pragma unroll
        for (int it = 0; it < 2; it++) {
            const int v = tid + it * 256;
            const int r = v >> 3, c16 = v & 7;
            const size_t gk = (size_t)(kb + r) * QKV_LD + 1024 + hcol + c16 * 8;
            const size_t gv = (size_t)(kb + r) * QKV_LD + 2048 + hcol + c16 * 8;
            const uint32_t sw = SW128((uint32_t)(r * 128 + c16 * 16));
            cp_async16(uS + sw,              QKV + gk);
            cp_async16(uS + ATT_KBYTES + sw, QKV + gv);
        }
        CP_ASYNC_COMMIT();
    };

    kvload(0, 0);   // group 1

    const uint32_t aRow = (uint32_t)((wid * 16 + (lane & 15)) * 128);
    const uint32_t aHalf = (uint32_t)((lane >> 4) * 16);
    uint32_t bRow[4];
#pragma unroll
    for (int ntp = 0; ntp < 4; ntp++)
        bRow[ntp] = (uint32_t)((ntp * 16 + ((lane >> 4) & 1) * 8 + (lane & 7)) * 128);
    const uint32_t bHalf = (uint32_t)(((lane >> 3) & 1) * 16);
    const uint32_t vRowPart = (uint32_t)((lane & 15) * 128);
    const uint32_t vColPart = (uint32_t)((lane >> 4) * 16);

    // ---- hoist Q fragments (loop-invariant) ----
    CP_ASYNC_WAIT(1);            // group 0 (Q) complete
    __syncthreads();
    uint32_t aq[4][4];
#pragma unroll
    for (int kk = 0; kk < 4; kk++)
        ldsm_x4(aq[kk], uQH + SW128(aRow + (uint32_t)(kk * 32) + aHalf));

    float oacc[8][4];
#pragma unroll
    for (int i = 0; i < 8; i++)
#pragma unroll
        for (int q = 0; q < 4; q++) oacc[i][q] = 0.f;
    float lacc[4] = {0.f, 0.f, 0.f, 0.f};
    const uint32_t onesh2 = 0x3C003C00u;          // (1.0h, 1.0h)
    const uint32_t bOnes[2] = {onesh2, onesh2};

    const int ntiles = S_LEN / 64;
    for (int t = 0; t < ntiles; t++) {
        const int s = t & 1;
        if (t + 1 < ntiles) {
            kvload(t + 1, s ^ 1);   // issue BEFORE wait
            CP_ASYNC_WAIT(1);
        } else {
            CP_ASYNC_WAIT(0);
        }
        __syncthreads();

        const uint32_t uS = uST + (uint32_t)s * ATT_STAGE;
        const uint32_t uKH = uS;
        const uint32_t uVH = uS + ATT_KBYTES;

        // ---- S = Q K^T (Q pre-scaled; result in log2 domain) ----
        float sacc[8][4];
#pragma unroll
        for (int i = 0; i < 8; i++)
#pragma unroll
            for (int q = 0; q < 4; q++) sacc[i][q] = 0.f;

#pragma unroll
        for (int kk = 0; kk < 4; kk++) {
            const uint32_t kOff = (uint32_t)(kk * 32);
#pragma unroll
            for (int ntp = 0; ntp < 4; ntp++) {
                uint32_t bh[4];
                ldsm_x4(bh, uKH + SW128(bRow[ntp] + kOff + bHalf));
                mma16816(sacc[2 * ntp],     aq[kk], &bh[0]);
                mma16816(sacc[2 * ntp + 1], aq[kk], &bh[2]);
            }
        }

        // ---- p = 2^s in fp16x2 ----
        uint32_t aP[4][4];
#pragma unroll
        for (int kc = 0; kc < 4; kc++) {
            const int ne = 2 * kc, no = 2 * kc + 1;
            aP[kc][0] = h2ex2(pack_f16x2(sacc[ne][0], sacc[ne][1]));
            aP[kc][1] = h2ex2(pack_f16x2(sacc[ne][2], sacc[ne][3]));
            aP[kc][2] = h2ex2(pack_f16x2(sacc[no][0], sacc[no][1]));
            aP[kc][3] = h2ex2(pack_f16x2(sacc[no][2], sacc[no][3]));
        }

        // ---- O += P V ; l += P @ ones (interleaved) ----
#pragma unroll
        for (int kc = 0; kc < 4; kc++) {
            const uint32_t kRow = (uint32_t)(kc * 16 * 128);
            mma16816(lacc, aP[kc], bOnes);
#pragma unroll
            for (int ntp = 0; ntp < 4; ntp++) {
                uint32_t vb[4];
                ldsm_x4_t(vb, uVH +
                    SW128(kRow + vRowPart + (uint32_t)(ntp * 32) + vColPart));
                mma16816(oacc[2 * ntp],     aP[kc], &vb[0]);
                mma16816(oacc[2 * ntp + 1], aP[kc], &vb[2]);
            }
        }
        __syncthreads();
    }

    // finalize: lacc[0]/lacc[2] hold the row sums (all B-cols equal)
    const float inv0 = 1.f / lacc[0];
    const float inv1 = 1.f / lacc[2];

    const int row0 = q0 + wid * 16 + (lane >> 2);
    const int row1 = row0 + 8;
    const int cbase = hcol + (lane & 3) * 2;
#pragma unroll
    for (int nt = 0; nt < 8; nt++) {
        const int col = cbase + nt * 8;
        *reinterpret_cast<__half2*>(Oh + (size_t)row0 * DMODEL + col) =
            __half2(__float2half(oacc[nt][0] * inv0),
                    __float2half(oacc[nt][1] * inv0));
        *reinterpret_cast<__half2*>(Oh + (size_t)row1 * DMODEL + col) =
            __half2(__float2half(oacc[nt][2] * inv1),
                    __float2half(oacc[nt][3] * inv1));
    }
}

// ---------------------------------------------------------------------------
// add + LayerNorm; fp32 + fp16 hi outputs
// ---------------------------------------------------------------------------
__global__ __launch_bounds__(256) void add_ln_kernel(
    const float* __restrict__ a, const float* __restrict__ b,
    const float* __restrict__ gamma, const float* __restrict__ beta,
    float* __restrict__ out, __half* __restrict__ oh)
{
    const int row = blockIdx.x;
    const int tid = threadIdx.x;
    const int c = tid * 4;

    const float4 va = *reinterpret_cast<const float4*>(&a[(size_t)row * DMODEL + c]);
    const float4 vb = *reinterpret_cast<const float4*>(&b[(size_t)row * DMODEL + c]);
    float v0 = va.x + vb.x, v1 = va.y + vb.y, v2 = va.z + vb.z, v3 = va.w + vb.w;

    float s = v0 + v1 + v2 + v3;
    float sq = v0 * v0 + v1 * v1 + v2 * v2 + v3 * v3;
#pragma unroll
    for (int o = 16; o > 0; o >>= 1) {
        s += __shfl_xor_sync(0xffffffffu, s, o);
        sq += __shfl_xor_sync(0xffffffffu, sq, o);
    }

    __shared__ float sh_s[8], sh_sq[8], sh_mean, sh_r;
    const int warp = tid >> 5, lane = tid & 31;
    if (lane == 0) { sh_s[warp] = s; sh_sq[warp] = sq; }
    __syncthreads();
    if (tid == 0) {
        float ts = 0.f, tq = 0.f;
#pragma unroll
        for (int i = 0; i < 8; i++) { ts += sh_s[i]; tq += sh_sq[i]; }
        const float mean = ts * (1.f / DMODEL);
        const float var = tq * (1.f / DMODEL) - mean * mean;
        sh_mean = mean;
        sh_r = rsqrtf(var + 1e-5f);
    }
    __syncthreads();
    const float mean = sh_mean, r = sh_r;

    const float4 g4 = *reinterpret_cast<const float4*>(&gamma[c]);
    const float4 b4 = *reinterpret_cast<const float4*>(&beta[c]);
    float4 o4;
    o4.x = (v0 - mean) * r * g4.x + b4.x;
    o4.y = (v1 - mean) * r * g4.y + b4.y;
    o4.z = (v2 - mean) * r * g4.z + b4.z;
    o4.w = (v3 - mean) * r * g4.w + b4.w;
    *reinterpret_cast<float4*>(&out[(size_t)row * DMODEL + c]) = o4;

    __half2* hp = reinterpret_cast<__half2*>(oh + (size_t)row * DMODEL + c);
    hp[0] = __half2(__float2half(o4.x), __float2half(o4.y));
    hp[1] = __half2(__float2half(o4.z), __float2half(o4.w));
}

// ---------------------------------------------------------------------------
// Launch
// ---------------------------------------------------------------------------
extern "C" void kernel_launch(void* const* d_in, const int* in_sizes, int n_in,
                              void* d_out, int out_size)
{
    const float* x      = (const float*)d_in[0];
    const float* q_in_w = (const float*)d_in[1];
    const float* q_in_b = (const float*)d_in[2];
    const float* k_in_w = (const float*)d_in[3];
    const float* k_in_b = (const float*)d_in[4];
    const float* v_in_w = (const float*)d_in[5];
    const float* v_in_b = (const float*)d_in[6];
    const float* out_w  = (const float*)d_in[7];
    const float* out_b  = (const float*)d_in[8];
    const float* ffn1_w = (const float*)d_in[9];
    const float* ffn1_b = (const float*)d_in[10];
    const float* ffn2_w = (const float*)d_in[11];
    const float* ffn2_b = (const float*)d_in[12];
    const float* n1_g   = (const float*)d_in[13];
    const float* n1_b   = (const float*)d_in[14];
    const float* n2_g   = (const float*)d_in[15];
    const float* n2_b   = (const float*)d_in[16];
    const float* q_out_w = (const float*)d_in[17];
    const float* q_out_b = (const float*)d_in[18];
    const float* k_out_w = (const float*)d_in[19];
    const float* k_out_b = (const float*)d_in[20];
    const float* v_out_w = (const float*)d_in[21];
    const float* v_out_b = (const float*)d_in[22];

    float* out = (float*)d_out;

    cudaFuncSetAttribute(gemm_tc, cudaFuncAttributeMaxDynamicSharedMemorySize,
                         GEMM_SMEM);
    cudaFuncSetAttribute(attn_tc, cudaFuncAttributeMaxDynamicSharedMemorySize,
                         ATT_SMEM);

    float* scratch = nullptr;
    cudaGetSymbolAddress((void**)&scratch, g_scratch);
    float* h0 = scratch + 0 * (size_t)SD;
    float* ff = scratch + 1 * (size_t)SD;
    float* h  = scratch + 2 * (size_t)SD;

    float* bias_cat = nullptr;
    cudaGetSymbolAddress((void**)&bias_cat, g_bias);

    float* y = out + 3 * (size_t)SD;

    __half* fp = nullptr;
    cudaGetSymbolAddress((void**)&fp, g_fp16);
    size_t off = 0;
    auto take1 = [&](size_t n) { __half* p = fp + off; off += n; return p; };

    // weights (contiguous, cvt_multi segment order), then x_h
    __half* qiw = take1((size_t)DMODEL * DMODEL);
    __half* kiw = take1((size_t)DMODEL * DMODEL);
    __half* viw = take1((size_t)DMODEL * DMODEL);
    __half* ow  = take1((size_t)DMODEL * DMODEL);
    __half* f1w = take1((size_t)DMODEL * DFF);
    __half* f2w = take1((size_t)DFF * DMODEL);
    __half* qow = take1((size_t)DMODEL * DMODEL);
    __half* kow = take1((size_t)DMODEL * DMODEL);
    __half* vow = take1((size_t)DMODEL * DMODEL);
    __half* x_h = take1(SD);
    // activations
    __half* qkv_h  = take1((size_t)S_LEN * 3072);
    __half* attn_h = take1(SD);
    __half* h_h    = take1(SD);
    __half* ff1_h  = take1(SF);
    __half* y_h    = take1(SD);
    (void)kiw; (void)viw; (void)kow; (void)vow;

    // conversions: one multi-segment kernel
    CvtSrcs srcs;
    srcs.p[0] = q_in_w;  srcs.p[1] = k_in_w;  srcs.p[2] = v_in_w;
    srcs.p[3] = out_w;   srcs.p[4] = ffn1_w;  srcs.p[5] = ffn2_w;
    srcs.p[6] = q_out_w; srcs.p[7] = k_out_w; srcs.p[8] = v_out_w;
    srcs.p[9] = x;
    cvt_multi<<<(CVT_TOTAL4 + 255) / 256, 256>>>(srcs, qiw);

    bias_cat_kernel<<<24, 256>>>(q_in_b, k_in_b, v_in_b,
                                 q_out_b, k_out_b, v_out_b, bias_cat);

    const dim3 g3(3072 / 128, S_LEN / 128);   // merged qkv
    const dim3 gD(DMODEL / 128, S_LEN / 128);
    const dim3 gF(DFF / 128, S_LEN / 128);

    // merged in-projection -> qkv_h [S, 3072]; Q cols pre-scaled (base-2)
    gemm_tc<<<g3, 256, GEMM_SMEM>>>(x_h, qiw, bias_cat,
                                    nullptr, qkv_h, S_LEN, 3072, DMODEL, 0, 0, 1);

    // attention -> attn_h
    attn_tc<<<dim3(S_LEN / 128, NHEAD), 256, ATT_SMEM>>>(qkv_h, attn_h);

    // out-proj + LN1
    gemm_tc<<<gD, 256, GEMM_SMEM>>>(attn_h, ow, out_b,
                                    h0, nullptr, S_LEN, DMODEL, DMODEL, 0, 0, 0);
    add_ln_kernel<<<S_LEN, 256>>>(x, h0, n1_g, n1_b, h, h_h);

    // FFN + LN2
    gemm_tc<<<gF, 256, GEMM_SMEM>>>(h_h, f1w, ffn1_b,
                                    nullptr, ff1_h, S_LEN, DFF, DMODEL, 1, 0, 0);
    gemm_tc<<<gD, 256, GEMM_SMEM>>>(ff1_h, f2w, ffn2_b,
                                    ff, nullptr, S_LEN, DMODEL, DFF, 0, 0, 0);
    add_ln_kernel<<<S_LEN, 256>>>(h, ff, n2_g, n2_b, y, y_h);

    // merged next-layer projections -> out[0..3*SD) via split3 remap
    gemm_tc<<<g3, 256, GEMM_SMEM>>>(y_h, qow, bias_cat + 3072,
                                    out, nullptr, S_LEN, 3072, DMODEL, 0, 1, 0);
}